// round 3
// baseline (speedup 1.0000x reference)
#include <cuda_runtime.h>
#include <math.h>

#define Hh 96
#define Ww 96
#define Bn 4
#define Cc 64
#define HW (Hh*Ww)
#define KK 9
#define CK 576
#define CIN2 130
#define PBLK 64            // pixels per deform block (linearized row-major)
#define VPITCH 68          // s_v row pitch in floats (bank-conflict pad)

// Scratch (device globals; no runtime allocation allowed)
__device__ float g_offset[Bn*18*HW];   // [B,18,HW]
__device__ float g_mod[Bn*9*HW];       // [B,9,HW] (2*sigmoid applied)
__device__ float g_fjt[Bn*HW*Cc];      // frame_j as [B,HW,C]
__device__ float g_w2[KK*16*64*4];     // w_reg as [tap][chquad][o][e]

// ---------------------------------------------------------------------------
// frame_j [B,C,H,W] -> [B,HW,C]
// ---------------------------------------------------------------------------
__global__ void k_transpose(const float* __restrict__ fj) {
    __shared__ float s[64][33];
    int b   = blockIdx.y;
    int hw0 = blockIdx.x * 32;
    int tid = threadIdx.x;
    int tx = tid & 31, ty = tid >> 5;
#pragma unroll
    for (int i = 0; i < 8; i++) {
        int c = ty + i * 8;
        s[c][tx] = fj[(size_t)(b * Cc + c) * HW + hw0 + tx];
    }
    __syncthreads();
    int ci = tid & 63, j4 = tid >> 6;
#pragma unroll
    for (int i = 0; i < 8; i++) {
        int j = j4 + i * 4;
        g_fjt[(size_t)(b * HW + hw0 + j) * Cc + ci] = s[ci][j];
    }
}

// ---------------------------------------------------------------------------
// w_reg [O=64, C=64, 9] -> g_w2[tap][q][o][e] = w_reg[o][4q+e][tap]
// ---------------------------------------------------------------------------
__global__ void k_w2(const float* __restrict__ w_reg) {
    int i = blockIdx.x * 256 + threadIdx.x;
    if (i < KK * 4096) {
        int tap = i >> 12;
        int r   = i & 4095;
        int q   = r >> 8;
        int r2  = r & 255;
        int o   = r2 >> 2;
        int e   = r2 & 3;
        g_w2[i] = w_reg[(o * 64 + q * 4 + e) * KK + tap];
    }
}

// ---------------------------------------------------------------------------
// Fused 3x3 conv: 130 in-ch -> 18 offset + 9 modulator channels.
// 32x4 pixel tile, 128 threads, 27 accumulators, double-buffered staging.
// Weight rows padded to 12 floats -> 9 weights fetched with 2 LDS.128 + LDS.32.
// ---------------------------------------------------------------------------
__global__ void __launch_bounds__(128) k_conv(
    const float* __restrict__ fi, const float* __restrict__ fj,
    const float* __restrict__ fl,
    const float* __restrict__ w_off, const float* __restrict__ b_off,
    const float* __restrict__ w_mod, const float* __restrict__ b_mod)
{
    __shared__ __align__(16) float s_in[2][6 * 34];
    __shared__ __align__(16) float s_w[2][27 * 12];
    int b  = blockIdx.z;
    int x0 = blockIdx.x * 32, y0 = blockIdx.y * 4;
    int tid = threadIdx.x;
    int tx = tid & 31, ty = tid >> 5;    // ty in 0..3

    float acc[27];
#pragma unroll
    for (int oc = 0; oc < 27; oc++) acc[oc] = 0.f;

    auto stage = [&](int cin, int buf) {
        const float* src = (cin < 64)  ? fi + (size_t)(b * 64 + cin) * HW
                         : (cin < 128) ? fj + (size_t)(b * 64 + cin - 64) * HW
                                       : fl + (size_t)(b * 2 + cin - 128) * HW;
        for (int i = tid; i < 6 * 34; i += 128) {
            int ly = i / 34, lx = i % 34;
            int gy = y0 + ly - 1, gx = x0 + lx - 1;
            s_in[buf][i] = (gy >= 0 && gy < Hh && gx >= 0 && gx < Ww)
                             ? src[gy * Ww + gx] : 0.f;
        }
        for (int i = tid; i < 243; i += 128) {
            int oc = i / 9, kk = i % 9;
            s_w[buf][oc * 12 + kk] = (oc < 18)
                ? w_off[(oc * CIN2 + cin) * 9 + kk]
                : w_mod[((oc - 18) * CIN2 + cin) * 9 + kk];
        }
    };

    stage(0, 0);
    __syncthreads();
    for (int cin = 0; cin < CIN2; cin++) {
        int cur = cin & 1;
        if (cin + 1 < CIN2) stage(cin + 1, cur ^ 1);

        float v[9];
#pragma unroll
        for (int ky = 0; ky < 3; ky++)
#pragma unroll
            for (int kx = 0; kx < 3; kx++)
                v[ky * 3 + kx] = s_in[cur][(ty + ky) * 34 + tx + kx];
#pragma unroll
        for (int oc = 0; oc < 27; oc++) {
            float4 wA = *(const float4*)&s_w[cur][oc * 12];
            float4 wB = *(const float4*)&s_w[cur][oc * 12 + 4];
            float  w8 = s_w[cur][oc * 12 + 8];
            float a = acc[oc];
            a += v[0] * wA.x + v[1] * wA.y + v[2] * wA.z + v[3] * wA.w;
            a += v[4] * wB.x + v[5] * wB.y + v[6] * wB.z + v[7] * wB.w;
            a += v[8] * w8;
            acc[oc] = a;
        }
        __syncthreads();
    }

    int y = y0 + ty, x = x0 + tx;
    int p = y * Ww + x;
#pragma unroll
    for (int oc = 0; oc < 18; oc++)
        g_offset[(size_t)(b * 18 + oc) * HW + p] = acc[oc] + b_off[oc];
#pragma unroll
    for (int mc = 0; mc < 9; mc++) {
        float z = acc[18 + mc] + b_mod[mc];
        g_mod[(size_t)(b * 9 + mc) * HW + p] = 2.f / (1.f + expf(-z));
    }
}

// ---------------------------------------------------------------------------
// Deformable conv: block = 64 pixels (linearized) x 64 outputs, 256 threads.
//   Contract: lane = pixel pair (lane, lane+32), warp = 8 output channels,
//   16 accumulators/thread. wv broadcast LDS amortized over 2 pixels.
// ---------------------------------------------------------------------------
__global__ void __launch_bounds__(256, 3) k_deform(float* __restrict__ out) {
    __shared__ __align__(16) float s_v[PBLK * VPITCH];     // 17408 B
    __shared__ __align__(16) float s_w[4096];              // 16384 B
    __shared__ float          s_cw[PBLK * 9][4];           //  9216 B
    __shared__ unsigned short s_ci[PBLK * 9][4];           //  4608 B

    int b   = blockIdx.y;
    int p0  = blockIdx.x * PBLK;
    int tid = threadIdx.x;

    // Phase 1: bilinear corner weights/indices for 64 pix x 9 taps
    for (int i = tid; i < PBLK * 9; i += 256) {
        int pix = i / 9, tap = i % 9;
        int p = p0 + pix;
        int y = p / Ww, x = p % Ww;
        int ky = tap / 3, kx = tap % 3;
        float offy = g_offset[(size_t)(b * 18 + 2 * tap)     * HW + p];
        float offx = g_offset[(size_t)(b * 18 + 2 * tap + 1) * HW + p];
        float m    = g_mod   [(size_t)(b * 9  + tap)         * HW + p];
        float py = (float)(y - 1 + ky) + offy;
        float px = (float)(x - 1 + kx) + offx;
        float fy = floorf(py), fx = floorf(px);
        int y0i = (int)fy, x0i = (int)fx;
        float wy = py - fy, wx = px - fx;
#pragma unroll
        for (int d = 0; d < 4; d++) {
            int dy = d >> 1, dx = d & 1;
            int yc = y0i + dy, xc = x0i + dx;
            bool ok = (yc >= 0) && (yc < Hh) && (xc >= 0) && (xc < Ww);
            float w = (dy ? wy : 1.f - wy) * (dx ? wx : 1.f - wx) * m;
            s_cw[i][d] = ok ? w : 0.f;
            int ycc = min(max(yc, 0), Hh - 1);
            int xcc = min(max(xc, 0), Ww - 1);
            s_ci[i][d] = (unsigned short)(ycc * Ww + xcc);
        }
    }

    float acc[16];
#pragma unroll
    for (int oi = 0; oi < 16; oi++) acc[oi] = 0.f;

    int lane = tid & 31;            // pixel (and pixel+32) for contract
    int o0   = (tid >> 5) * 8;      // output group for contract
    int gp   = tid >> 3;            // gather pixel base (0..31)
    int gq   = tid & 7;             // gather channel-quad base
    const float* fb = g_fjt + (size_t)b * HW * Cc;

    __syncthreads();

    for (int tap = 0; tap < 9; tap++) {
        // stage weight tap tile [16 q][64 o][4 e] -> s_w (coalesced)
        {
            const float4* src = (const float4*)(g_w2 + tap * 4096);
            float4* dst = (float4*)s_w;
#pragma unroll
            for (int i = 0; i < 4; i++)
                dst[tid + i * 256] = src[tid + i * 256];
        }
        // gather: 2 pixels x 2 channel-quads per thread
#pragma unroll
        for (int ph = 0; ph < 2; ph++) {
            int pix = gp + 32 * ph;
            int j = pix * 9 + tap;
            float w0 = s_cw[j][0], w1 = s_cw[j][1];
            float w2 = s_cw[j][2], w3 = s_cw[j][3];
            const float* pp0 = fb + (size_t)s_ci[j][0] * Cc;
            const float* pp1 = fb + (size_t)s_ci[j][1] * Cc;
            const float* pp2 = fb + (size_t)s_ci[j][2] * Cc;
            const float* pp3 = fb + (size_t)s_ci[j][3] * Cc;
#pragma unroll
            for (int qq = 0; qq < 2; qq++) {
                int q = gq + qq * 8;
                float4 f0 = *(const float4*)(pp0 + q * 4);
                float4 f1 = *(const float4*)(pp1 + q * 4);
                float4 f2 = *(const float4*)(pp2 + q * 4);
                float4 f3 = *(const float4*)(pp3 + q * 4);
                float4 v;
                v.x = w0 * f0.x + w1 * f1.x + w2 * f2.x + w3 * f3.x;
                v.y = w0 * f0.y + w1 * f1.y + w2 * f2.y + w3 * f3.y;
                v.z = w0 * f0.z + w1 * f1.z + w2 * f2.z + w3 * f3.z;
                v.w = w0 * f0.w + w1 * f1.w + w2 * f2.w + w3 * f3.w;
                *(float4*)(s_v + pix * VPITCH + q * 4) = v;
            }
        }
        __syncthreads();

        // contract: 2 pixels x 8 outputs per thread
        {
            const float* va = s_v + lane * VPITCH;
            const float* vb = s_v + (lane + 32) * VPITCH;
#pragma unroll 4
            for (int q = 0; q < 16; q++) {
                float4 ta = *(const float4*)(va + q * 4);
                float4 tb = *(const float4*)(vb + q * 4);
#pragma unroll
                for (int oi = 0; oi < 8; oi++) {
                    float4 wv = *(const float4*)(s_w + (q * 64 + o0 + oi) * 4);
                    acc[oi]     += ta.x * wv.x + ta.y * wv.y
                                 + ta.z * wv.z + ta.w * wv.w;
                    acc[8 + oi] += tb.x * wv.x + tb.y * wv.y
                                 + tb.z * wv.z + tb.w * wv.w;
                }
            }
        }
        __syncthreads();
    }

    // epilogue: coalesced stores (HW is contiguous per output channel)
#pragma unroll
    for (int oi = 0; oi < 8; oi++) {
        size_t base = (size_t)(b * 64 + o0 + oi) * HW + p0;
        out[base + lane]      = acc[oi];
        out[base + 32 + lane] = acc[8 + oi];
    }
}

// ---------------------------------------------------------------------------
extern "C" void kernel_launch(void* const* d_in, const int* in_sizes, int n_in,
                              void* d_out, int out_size) {
    const float* frame_i = (const float*)d_in[0];
    const float* frame_j = (const float*)d_in[1];
    const float* flow_ij = (const float*)d_in[2];
    const float* w_off   = (const float*)d_in[3];
    const float* b_off   = (const float*)d_in[4];
    const float* w_mod   = (const float*)d_in[5];
    const float* b_mod   = (const float*)d_in[6];
    const float* w_reg   = (const float*)d_in[7];
    float* out = (float*)d_out;

    k_transpose<<<dim3(HW / 32, Bn), 256>>>(frame_j);
    k_w2<<<(KK * 4096 + 255) / 256, 256>>>(w_reg);
    k_conv<<<dim3(Ww / 32, Hh / 4, Bn), 128>>>(frame_i, frame_j, flow_ij,
                                               w_off, b_off, w_mod, b_mod);
    k_deform<<<dim3(HW / PBLK, Bn), 256>>>(out);
}

// round 5
// speedup vs baseline: 1.4099x; 1.4099x over previous
#include <cuda_runtime.h>
#include <cstdint>
#include <math.h>

#define Hh 96
#define Ww 96
#define Bn 4
#define Cc 64
#define HW (Hh*Ww)
#define KK 9
#define CIN2 130
#define PBLK 64            // pixels per deform block
#define VPITCH 68          // s_v row pitch (bank pad)
#define NCH 65             // conv pipeline stages (2 cin each)

// Scratch (device globals)
__device__ float g_offset[Bn*18*HW];
__device__ float g_mod[Bn*9*HW];
__device__ float g_fjt[Bn*HW*Cc];      // frame_j as [B,HW,C]
__device__ float g_w2[KK*16*64*4];     // w_reg as [tap][chquad][o][e]
__device__ float g_wc[CIN2*27*12];     // conv weights as [cin][oc*12+kk]

// ---------------------------------------------------------------------------
__device__ __forceinline__ void cpa4(unsigned int dst, const void* src, bool pred) {
    int sz = pred ? 4 : 0;
    asm volatile("cp.async.ca.shared.global [%0], [%1], 4, %2;\n"
                 :: "r"(dst), "l"(src), "r"(sz));
}
__device__ __forceinline__ void cpa_commit() {
    asm volatile("cp.async.commit_group;\n");
}

// ---------------------------------------------------------------------------
// frame_j [B,C,H,W] -> [B,HW,C]
// ---------------------------------------------------------------------------
__global__ void k_transpose(const float* __restrict__ fj) {
    __shared__ float s[64][33];
    int b   = blockIdx.y;
    int hw0 = blockIdx.x * 32;
    int tid = threadIdx.x;
    int tx = tid & 31, ty = tid >> 5;
#pragma unroll
    for (int i = 0; i < 8; i++) {
        int c = ty + i * 8;
        s[c][tx] = fj[(size_t)(b * Cc + c) * HW + hw0 + tx];
    }
    __syncthreads();
    int ci = tid & 63, j4 = tid >> 6;
#pragma unroll
    for (int i = 0; i < 8; i++) {
        int j = j4 + i * 4;
        g_fjt[(size_t)(b * HW + hw0 + j) * Cc + ci] = s[ci][j];
    }
}

// ---------------------------------------------------------------------------
// w_reg [O=64,C=64,9] -> g_w2[tap][q][o][e] = w_reg[o][4q+e][tap]
// ---------------------------------------------------------------------------
__global__ void k_w2(const float* __restrict__ w_reg) {
    int i = blockIdx.x * 256 + threadIdx.x;
    if (i < KK * 4096) {
        int tap = i >> 12;
        int r   = i & 4095;
        int q   = r >> 8;
        int r2  = r & 255;
        int o   = r2 >> 2;
        int e   = r2 & 3;
        g_w2[i] = w_reg[(o * 64 + q * 4 + e) * KK + tap];
    }
}

// ---------------------------------------------------------------------------
// Conv weights -> g_wc[cin][oc*12+kk]  (rows padded 9->12)
// ---------------------------------------------------------------------------
__global__ void k_wc(const float* __restrict__ w_off,
                     const float* __restrict__ w_mod) {
    int i = blockIdx.x * 256 + threadIdx.x;
    if (i < CIN2 * 27 * 12) {
        int cin = i / (27 * 12);
        int r   = i % (27 * 12);
        int oc  = r / 12, kk = r % 12;
        float v = 0.f;
        if (kk < 9)
            v = (oc < 18) ? w_off[(oc * CIN2 + cin) * 9 + kk]
                          : w_mod[((oc - 18) * CIN2 + cin) * 9 + kk];
        g_wc[i] = v;
    }
}

// ---------------------------------------------------------------------------
// Fused 3x3 conv, cp.async 2-deep pipeline, 2 cin per stage.
// 32x8 pixel tile, 256 threads, 27 accumulators.
// ---------------------------------------------------------------------------
__global__ void __launch_bounds__(256) k_conv(
    const float* __restrict__ fi, const float* __restrict__ fj,
    const float* __restrict__ fl,
    const float* __restrict__ b_off, const float* __restrict__ b_mod)
{
    __shared__ __align__(16) float s_in[2][2][340];
    __shared__ __align__(16) float s_w[2][2][324];
    int b  = blockIdx.z;
    int x0 = blockIdx.x * 32, y0 = blockIdx.y * 8;
    int tid = threadIdx.x;
    int tx = tid & 31, ty = tid >> 5;

    auto stage = [&](int s, int buf) {
#pragma unroll
        for (int c2 = 0; c2 < 2; c2++) {
            int cin = s * 2 + c2;
            const float* src = (cin < 64)  ? fi + (size_t)(b * 64 + cin) * HW
                             : (cin < 128) ? fj + (size_t)(b * 64 + cin - 64) * HW
                                           : fl + (size_t)(b * 2 + cin - 128) * HW;
            for (int i = tid; i < 340; i += 256) {
                int ly = i / 34, lx = i % 34;
                int gy = y0 + ly - 1, gx = x0 + lx - 1;
                bool ok = (gy >= 0 && gy < Hh && gx >= 0 && gx < Ww);
                const float* g = src + (ok ? (gy * Ww + gx) : 0);
                cpa4((unsigned int)__cvta_generic_to_shared(&s_in[buf][c2][i]), g, ok);
            }
            const float* wsrc = g_wc + (size_t)cin * 324;
            for (int i = tid; i < 324; i += 256)
                cpa4((unsigned int)__cvta_generic_to_shared(&s_w[buf][c2][i]),
                     wsrc + i, true);
        }
    };

    float acc[27];
#pragma unroll
    for (int oc = 0; oc < 27; oc++) acc[oc] = 0.f;

    stage(0, 0); cpa_commit();
    stage(1, 1); cpa_commit();

    for (int s = 0; s < NCH; s++) {
        if (s == NCH - 1) asm volatile("cp.async.wait_group 0;\n");
        else              asm volatile("cp.async.wait_group 1;\n");
        __syncthreads();
        int buf = s & 1;
#pragma unroll
        for (int c2 = 0; c2 < 2; c2++) {
            float v[9];
#pragma unroll
            for (int ky = 0; ky < 3; ky++)
#pragma unroll
                for (int kx = 0; kx < 3; kx++)
                    v[ky * 3 + kx] = s_in[buf][c2][(ty + ky) * 34 + tx + kx];
#pragma unroll
            for (int oc = 0; oc < 27; oc++) {
                const float* wr = &s_w[buf][c2][oc * 12];
                float4 wA = *(const float4*)wr;
                float4 wB = *(const float4*)(wr + 4);
                float  w8 = wr[8];
                float a = acc[oc];
                a += v[0] * wA.x + v[1] * wA.y + v[2] * wA.z + v[3] * wA.w;
                a += v[4] * wB.x + v[5] * wB.y + v[6] * wB.z + v[7] * wB.w;
                a += v[8] * w8;
                acc[oc] = a;
            }
        }
        __syncthreads();
        if (s + 2 < NCH) { stage(s + 2, buf); cpa_commit(); }
    }

    int y = y0 + ty, x = x0 + tx;
    int p = y * Ww + x;
#pragma unroll
    for (int oc = 0; oc < 18; oc++)
        g_offset[(size_t)(b * 18 + oc) * HW + p] = acc[oc] + b_off[oc];
#pragma unroll
    for (int mc = 0; mc < 9; mc++) {
        float z = acc[18 + mc] + b_mod[mc];
        g_mod[(size_t)(b * 9 + mc) * HW + p] = 2.f / (1.f + expf(-z));
    }
}

// ---------------------------------------------------------------------------
// Deformable conv: block = 64 pixels x 64 outputs, 256 threads.
// ---------------------------------------------------------------------------
__global__ void __launch_bounds__(256, 3) k_deform(float* __restrict__ out) {
    __shared__ __align__(16) float s_v[PBLK * VPITCH];
    __shared__ __align__(16) float s_w[4096];
    __shared__ float          s_cw[PBLK * 9][4];
    __shared__ unsigned short s_ci[PBLK * 9][4];

    int b   = blockIdx.y;
    int p0  = blockIdx.x * PBLK;
    int tid = threadIdx.x;

    for (int i = tid; i < PBLK * 9; i += 256) {
        int pix = i / 9, tap = i % 9;
        int p = p0 + pix;
        int y = p / Ww, x = p % Ww;
        int ky = tap / 3, kx = tap % 3;
        float offy = g_offset[(size_t)(b * 18 + 2 * tap)     * HW + p];
        float offx = g_offset[(size_t)(b * 18 + 2 * tap + 1) * HW + p];
        float m    = g_mod   [(size_t)(b * 9  + tap)         * HW + p];
        float py = (float)(y - 1 + ky) + offy;
        float px = (float)(x - 1 + kx) + offx;
        float fy = floorf(py), fx = floorf(px);
        int y0i = (int)fy, x0i = (int)fx;
        float wy = py - fy, wx = px - fx;
#pragma unroll
        for (int d = 0; d < 4; d++) {
            int dy = d >> 1, dx = d & 1;
            int yc = y0i + dy, xc = x0i + dx;
            bool ok = (yc >= 0) && (yc < Hh) && (xc >= 0) && (xc < Ww);
            float w = (dy ? wy : 1.f - wy) * (dx ? wx : 1.f - wx) * m;
            s_cw[i][d] = ok ? w : 0.f;
            int ycc = min(max(yc, 0), Hh - 1);
            int xcc = min(max(xc, 0), Ww - 1);
            s_ci[i][d] = (unsigned short)(ycc * Ww + xcc);
        }
    }

    float acc[16];
#pragma unroll
    for (int oi = 0; oi < 16; oi++) acc[oi] = 0.f;

    int lane = tid & 31;
    int o0   = (tid >> 5) * 8;
    int gp   = tid >> 3;
    int gq   = tid & 7;
    const float* fb = g_fjt + (size_t)b * HW * Cc;

    __syncthreads();

    for (int tap = 0; tap < 9; tap++) {
        {
            const float4* src = (const float4*)(g_w2 + tap * 4096);
            float4* dst = (float4*)s_w;
#pragma unroll
            for (int i = 0; i < 4; i++)
                dst[tid + i * 256] = src[tid + i * 256];
        }
#pragma unroll
        for (int ph = 0; ph < 2; ph++) {
            int pix = gp + 32 * ph;
            int j = pix * 9 + tap;
            float w0 = s_cw[j][0], w1 = s_cw[j][1];
            float w2 = s_cw[j][2], w3 = s_cw[j][3];
            const float* pp0 = fb + (size_t)s_ci[j][0] * Cc;
            const float* pp1 = fb + (size_t)s_ci[j][1] * Cc;
            const float* pp2 = fb + (size_t)s_ci[j][2] * Cc;
            const float* pp3 = fb + (size_t)s_ci[j][3] * Cc;
#pragma unroll
            for (int qq = 0; qq < 2; qq++) {
                int q = gq + qq * 8;
                float4 f0 = *(const float4*)(pp0 + q * 4);
                float4 f1 = *(const float4*)(pp1 + q * 4);
                float4 f2 = *(const float4*)(pp2 + q * 4);
                float4 f3 = *(const float4*)(pp3 + q * 4);
                float4 v;
                v.x = w0 * f0.x + w1 * f1.x + w2 * f2.x + w3 * f3.x;
                v.y = w0 * f0.y + w1 * f1.y + w2 * f2.y + w3 * f3.y;
                v.z = w0 * f0.z + w1 * f1.z + w2 * f2.z + w3 * f3.z;
                v.w = w0 * f0.w + w1 * f1.w + w2 * f2.w + w3 * f3.w;
                *(float4*)(s_v + pix * VPITCH + q * 4) = v;
            }
        }
        __syncthreads();

        {
            const float* va = s_v + lane * VPITCH;
            const float* vb = s_v + (lane + 32) * VPITCH;
#pragma unroll 4
            for (int q = 0; q < 16; q++) {
                float4 ta = *(const float4*)(va + q * 4);
                float4 tb = *(const float4*)(vb + q * 4);
#pragma unroll
                for (int oi = 0; oi < 8; oi++) {
                    float4 wv = *(const float4*)(s_w + (q * 64 + o0 + oi) * 4);
                    acc[oi]     += ta.x * wv.x + ta.y * wv.y
                                 + ta.z * wv.z + ta.w * wv.w;
                    acc[8 + oi] += tb.x * wv.x + tb.y * wv.y
                                 + tb.z * wv.z + tb.w * wv.w;
                }
            }
        }
        __syncthreads();
    }

#pragma unroll
    for (int oi = 0; oi < 8; oi++) {
        size_t base = (size_t)(b * 64 + o0 + oi) * HW + p0;
        out[base + lane]      = acc[oi];
        out[base + 32 + lane] = acc[8 + oi];
    }
}

// ---------------------------------------------------------------------------
extern "C" void kernel_launch(void* const* d_in, const int* in_sizes, int n_in,
                              void* d_out, int out_size) {
    const float* frame_i = (const float*)d_in[0];
    const float* frame_j = (const float*)d_in[1];
    const float* flow_ij = (const float*)d_in[2];
    const float* w_off   = (const float*)d_in[3];
    const float* b_off   = (const float*)d_in[4];
    const float* w_mod   = (const float*)d_in[5];
    const float* b_mod   = (const float*)d_in[6];
    const float* w_reg   = (const float*)d_in[7];
    float* out = (float*)d_out;

    k_transpose<<<dim3(HW / 32, Bn), 256>>>(frame_j);
    k_w2<<<(KK * 4096 + 255) / 256, 256>>>(w_reg);
    k_wc<<<(CIN2 * 27 * 12 + 255) / 256, 256>>>(w_off, w_mod);
    k_conv<<<dim3(Ww / 32, Hh / 8, Bn), 256>>>(frame_i, frame_j, flow_ij,
                                               b_off, b_mod);
    k_deform<<<dim3(HW / PBLK, Bn), 256>>>(out);
}

// round 6
// speedup vs baseline: 1.4566x; 1.0331x over previous
#include <cuda_runtime.h>
#include <cstdint>
#include <math.h>

#define Hh 96
#define Ww 96
#define Bn 4
#define Cc 64
#define HW (Hh*Ww)
#define KK 9
#define CIN2 130
#define PBLK 64            // pixels per deform block
#define VPITCH 68          // s_v row pitch (bank pad)
#define NST 33             // conv pipeline stages (2 cin each, 65 cins/half)

// Scratch (device globals)
__device__ float g_offset[Bn*18*HW];
__device__ float g_mod[Bn*9*HW];
__device__ float g_fjt[Bn*HW*Cc];      // frame_j as [B,HW,C]
__device__ float g_w2[KK*16*64*4];     // w_reg as [tap][chquad][o][e]
__device__ float g_wc[CIN2*27*12];     // conv weights as [cin][oc*12+kk], kk>=9 zero
__device__ float g_part[8*27*HW];      // conv partials [b*2+half][27][HW]

// ---------------------------------------------------------------------------
__device__ __forceinline__ void cpa4(unsigned int dst, const void* src, bool pred) {
    int sz = pred ? 4 : 0;
    asm volatile("cp.async.ca.shared.global [%0], [%1], 4, %2;\n"
                 :: "r"(dst), "l"(src), "r"(sz));
}
__device__ __forceinline__ void cpa_commit() {
    asm volatile("cp.async.commit_group;\n");
}
__device__ __forceinline__ unsigned long long ffma2(
    unsigned long long a, unsigned long long b, unsigned long long c) {
    unsigned long long d;
    asm("fma.rn.f32x2 %0, %1, %2, %3;" : "=l"(d) : "l"(a), "l"(b), "l"(c));
    return d;
}
__device__ __forceinline__ unsigned long long pack2(float lo, float hi) {
    unsigned long long d;
    asm("mov.b64 %0, {%1, %2};" : "=l"(d) : "f"(lo), "f"(hi));
    return d;
}
__device__ __forceinline__ float2 unpack2(unsigned long long v) {
    float lo, hi;
    asm("mov.b64 {%0, %1}, %2;" : "=f"(lo), "=f"(hi) : "l"(v));
    return make_float2(lo, hi);
}

// ---------------------------------------------------------------------------
// frame_j [B,C,H,W] -> [B,HW,C]
// ---------------------------------------------------------------------------
__global__ void k_transpose(const float* __restrict__ fj) {
    __shared__ float s[64][33];
    int b   = blockIdx.y;
    int hw0 = blockIdx.x * 32;
    int tid = threadIdx.x;
    int tx = tid & 31, ty = tid >> 5;
#pragma unroll
    for (int i = 0; i < 8; i++) {
        int c = ty + i * 8;
        s[c][tx] = fj[(size_t)(b * Cc + c) * HW + hw0 + tx];
    }
    __syncthreads();
    int ci = tid & 63, j4 = tid >> 6;
#pragma unroll
    for (int i = 0; i < 8; i++) {
        int j = j4 + i * 4;
        g_fjt[(size_t)(b * HW + hw0 + j) * Cc + ci] = s[ci][j];
    }
}

// ---------------------------------------------------------------------------
// w_reg [O=64,C=64,9] -> g_w2[tap][q][o][e] = w_reg[o][4q+e][tap]
// ---------------------------------------------------------------------------
__global__ void k_w2(const float* __restrict__ w_reg) {
    int i = blockIdx.x * 256 + threadIdx.x;
    if (i < KK * 4096) {
        int tap = i >> 12;
        int r   = i & 4095;
        int q   = r >> 8;
        int r2  = r & 255;
        int o   = r2 >> 2;
        int e   = r2 & 3;
        g_w2[i] = w_reg[(o * 64 + q * 4 + e) * KK + tap];
    }
}

// ---------------------------------------------------------------------------
// Conv weights -> g_wc[cin][oc*12+kk]  (rows padded 9->12, tail zero)
// ---------------------------------------------------------------------------
__global__ void k_wc(const float* __restrict__ w_off,
                     const float* __restrict__ w_mod) {
    int i = blockIdx.x * 256 + threadIdx.x;
    if (i < CIN2 * 27 * 12) {
        int cin = i / (27 * 12);
        int r   = i % (27 * 12);
        int oc  = r / 12, kk = r % 12;
        float v = 0.f;
        if (kk < 9)
            v = (oc < 18) ? w_off[(oc * CIN2 + cin) * 9 + kk]
                          : w_mod[((oc - 18) * CIN2 + cin) * 9 + kk];
        g_wc[i] = v;
    }
}

// ---------------------------------------------------------------------------
// Fused 3x3 conv (half of cin reduction per block), packed f32x2 FMA,
// cp.async triple-buffer pipeline. 32x8 tile, 256 threads, grid z = b*2+half.
// ---------------------------------------------------------------------------
__global__ void __launch_bounds__(256, 2) k_conv(
    const float* __restrict__ fi, const float* __restrict__ fj,
    const float* __restrict__ fl)
{
    __shared__ __align__(16) float s_in[3][2][340];
    __shared__ __align__(16) float s_w[3][2][324];
    int z  = blockIdx.z;
    int b  = z >> 1, half = z & 1;
    int cin_base = half * 65;
    int x0 = blockIdx.x * 32, y0 = blockIdx.y * 8;
    int tid = threadIdx.x;
    int tx = tid & 31, ty = tid >> 5;

    auto stage = [&](int s, int buf) {
#pragma unroll
        for (int c2 = 0; c2 < 2; c2++) {
            int lc = s * 2 + c2;
            bool vcin = (lc < 65);
            int cin = cin_base + (vcin ? lc : 0);
            const float* src = (cin < 64)  ? fi + (size_t)(b * 64 + cin) * HW
                             : (cin < 128) ? fj + (size_t)(b * 64 + cin - 64) * HW
                                           : fl + (size_t)(b * 2 + cin - 128) * HW;
            for (int i = tid; i < 340; i += 256) {
                int ly = i / 34, lx = i % 34;
                int gy = y0 + ly - 1, gx = x0 + lx - 1;
                bool ok = vcin && (gy >= 0 && gy < Hh && gx >= 0 && gx < Ww);
                const float* g = src + (ok ? (gy * Ww + gx) : 0);
                cpa4((unsigned int)__cvta_generic_to_shared(&s_in[buf][c2][i]), g, ok);
            }
            const float* wsrc = g_wc + (size_t)cin * 324;
            for (int i = tid; i < 324; i += 256)
                cpa4((unsigned int)__cvta_generic_to_shared(&s_w[buf][c2][i]),
                     wsrc + i, vcin);
        }
    };

    unsigned long long acc2[27];
#pragma unroll
    for (int oc = 0; oc < 27; oc++) acc2[oc] = 0ull;

    stage(0, 0); cpa_commit();
    stage(1, 1); cpa_commit();

    for (int s = 0; s < NST; s++) {
        if (s < NST - 1) asm volatile("cp.async.wait_group 1;\n");
        else             asm volatile("cp.async.wait_group 0;\n");
        __syncthreads();
        int buf = s % 3;
#pragma unroll
        for (int c2 = 0; c2 < 2; c2++) {
            float v[9];
#pragma unroll
            for (int ky = 0; ky < 3; ky++)
#pragma unroll
                for (int kx = 0; kx < 3; kx++)
                    v[ky * 3 + kx] = s_in[buf][c2][(ty + ky) * 34 + tx + kx];
            unsigned long long v01 = pack2(v[0], v[1]);
            unsigned long long v23 = pack2(v[2], v[3]);
            unsigned long long v45 = pack2(v[4], v[5]);
            unsigned long long v67 = pack2(v[6], v[7]);
            unsigned long long v89 = pack2(v[8], 0.f);
#pragma unroll
            for (int oc = 0; oc < 27; oc++) {
                const float* wr = &s_w[buf][c2][oc * 12];
                ulonglong2 wab = *(const ulonglong2*)wr;
                ulonglong2 wcd = *(const ulonglong2*)(wr + 4);
                unsigned long long w89 = *(const unsigned long long*)(wr + 8);
                unsigned long long a = acc2[oc];
                a = ffma2(v01, wab.x, a);
                a = ffma2(v23, wab.y, a);
                a = ffma2(v45, wcd.x, a);
                a = ffma2(v67, wcd.y, a);
                a = ffma2(v89, w89, a);
                acc2[oc] = a;
            }
        }
        if (s + 2 < NST) { stage(s + 2, (s + 2) % 3); cpa_commit(); }
    }

    int p = (y0 + ty) * Ww + x0 + tx;
#pragma unroll
    for (int oc = 0; oc < 27; oc++) {
        float2 u = unpack2(acc2[oc]);
        g_part[((size_t)z * 27 + oc) * HW + p] = u.x + u.y;
    }
}

// ---------------------------------------------------------------------------
// Combine conv halves + bias (+ 2*sigmoid for modulator)
// ---------------------------------------------------------------------------
__global__ void k_post(const float* __restrict__ b_off,
                       const float* __restrict__ b_mod) {
    int t = blockIdx.x * 256 + threadIdx.x;   // 0 .. Bn*HW-1
    int b = t / HW, p = t % HW;
    const float* p0 = g_part + ((size_t)(b * 2)     * 27) * HW + p;
    const float* p1 = g_part + ((size_t)(b * 2 + 1) * 27) * HW + p;
#pragma unroll
    for (int oc = 0; oc < 18; oc++)
        g_offset[(size_t)(b * 18 + oc) * HW + p] =
            p0[oc * HW] + p1[oc * HW] + b_off[oc];
#pragma unroll
    for (int mc = 0; mc < 9; mc++) {
        float zz = p0[(18 + mc) * HW] + p1[(18 + mc) * HW] + b_mod[mc];
        g_mod[(size_t)(b * 9 + mc) * HW + p] = 2.f / (1.f + expf(-zz));
    }
}

// ---------------------------------------------------------------------------
// Deformable conv: block = 64 pixels x 64 outputs, 256 threads.
// Contract uses packed f32x2 FMA (even/odd channel partials).
// ---------------------------------------------------------------------------
__global__ void __launch_bounds__(256, 3) k_deform(float* __restrict__ out) {
    __shared__ __align__(16) float s_v[PBLK * VPITCH];
    __shared__ __align__(16) float s_w[4096];
    __shared__ float          s_cw[PBLK * 9][4];
    __shared__ unsigned short s_ci[PBLK * 9][4];

    int b   = blockIdx.y;
    int p0  = blockIdx.x * PBLK;
    int tid = threadIdx.x;

    for (int i = tid; i < PBLK * 9; i += 256) {
        int pix = i / 9, tap = i % 9;
        int p = p0 + pix;
        int y = p / Ww, x = p % Ww;
        int ky = tap / 3, kx = tap % 3;
        float offy = g_offset[(size_t)(b * 18 + 2 * tap)     * HW + p];
        float offx = g_offset[(size_t)(b * 18 + 2 * tap + 1) * HW + p];
        float m    = g_mod   [(size_t)(b * 9  + tap)         * HW + p];
        float py = (float)(y - 1 + ky) + offy;
        float px = (float)(x - 1 + kx) + offx;
        float fy = floorf(py), fx = floorf(px);
        int y0i = (int)fy, x0i = (int)fx;
        float wy = py - fy, wx = px - fx;
#pragma unroll
        for (int d = 0; d < 4; d++) {
            int dy = d >> 1, dx = d & 1;
            int yc = y0i + dy, xc = x0i + dx;
            bool ok = (yc >= 0) && (yc < Hh) && (xc >= 0) && (xc < Ww);
            float w = (dy ? wy : 1.f - wy) * (dx ? wx : 1.f - wx) * m;
            s_cw[i][d] = ok ? w : 0.f;
            int ycc = min(max(yc, 0), Hh - 1);
            int xcc = min(max(xc, 0), Ww - 1);
            s_ci[i][d] = (unsigned short)(ycc * Ww + xcc);
        }
    }

    unsigned long long a2[16];
#pragma unroll
    for (int oi = 0; oi < 16; oi++) a2[oi] = 0ull;

    int lane = tid & 31;
    int o0   = (tid >> 5) * 8;
    int gp   = tid >> 3;
    int gq   = tid & 7;
    const float* fb = g_fjt + (size_t)b * HW * Cc;

    __syncthreads();

    for (int tap = 0; tap < 9; tap++) {
        {
            const float4* src = (const float4*)(g_w2 + tap * 4096);
            float4* dst = (float4*)s_w;
#pragma unroll
            for (int i = 0; i < 4; i++)
                dst[tid + i * 256] = src[tid + i * 256];
        }
#pragma unroll
        for (int ph = 0; ph < 2; ph++) {
            int pix = gp + 32 * ph;
            int j = pix * 9 + tap;
            float w0 = s_cw[j][0], w1 = s_cw[j][1];
            float w2 = s_cw[j][2], w3 = s_cw[j][3];
            const float* pp0 = fb + (size_t)s_ci[j][0] * Cc;
            const float* pp1 = fb + (size_t)s_ci[j][1] * Cc;
            const float* pp2 = fb + (size_t)s_ci[j][2] * Cc;
            const float* pp3 = fb + (size_t)s_ci[j][3] * Cc;
#pragma unroll
            for (int qq = 0; qq < 2; qq++) {
                int q = gq + qq * 8;
                float4 f0 = *(const float4*)(pp0 + q * 4);
                float4 f1 = *(const float4*)(pp1 + q * 4);
                float4 f2 = *(const float4*)(pp2 + q * 4);
                float4 f3 = *(const float4*)(pp3 + q * 4);
                float4 v;
                v.x = w0 * f0.x + w1 * f1.x + w2 * f2.x + w3 * f3.x;
                v.y = w0 * f0.y + w1 * f1.y + w2 * f2.y + w3 * f3.y;
                v.z = w0 * f0.z + w1 * f1.z + w2 * f2.z + w3 * f3.z;
                v.w = w0 * f0.w + w1 * f1.w + w2 * f2.w + w3 * f3.w;
                *(float4*)(s_v + pix * VPITCH + q * 4) = v;
            }
        }
        __syncthreads();

        {
            const float* va = s_v + lane * VPITCH;
            const float* vb = s_v + (lane + 32) * VPITCH;
#pragma unroll 4
            for (int q = 0; q < 16; q++) {
                ulonglong2 ta = *(const ulonglong2*)(va + q * 4);
                ulonglong2 tb = *(const ulonglong2*)(vb + q * 4);
#pragma unroll
                for (int oi = 0; oi < 8; oi++) {
                    ulonglong2 wv = *(const ulonglong2*)(s_w + (q * 64 + o0 + oi) * 4);
                    unsigned long long x = a2[oi];
                    x = ffma2(ta.x, wv.x, x);
                    x = ffma2(ta.y, wv.y, x);
                    a2[oi] = x;
                    unsigned long long y2 = a2[8 + oi];
                    y2 = ffma2(tb.x, wv.x, y2);
                    y2 = ffma2(tb.y, wv.y, y2);
                    a2[8 + oi] = y2;
                }
            }
        }
        __syncthreads();
    }

#pragma unroll
    for (int oi = 0; oi < 8; oi++) {
        size_t base = (size_t)(b * 64 + o0 + oi) * HW + p0;
        float2 ua = unpack2(a2[oi]);
        float2 ub = unpack2(a2[8 + oi]);
        out[base + lane]      = ua.x + ua.y;
        out[base + 32 + lane] = ub.x + ub.y;
    }
}

// ---------------------------------------------------------------------------
extern "C" void kernel_launch(void* const* d_in, const int* in_sizes, int n_in,
                              void* d_out, int out_size) {
    const float* frame_i = (const float*)d_in[0];
    const float* frame_j = (const float*)d_in[1];
    const float* flow_ij = (const float*)d_in[2];
    const float* w_off   = (const float*)d_in[3];
    const float* b_off   = (const float*)d_in[4];
    const float* w_mod   = (const float*)d_in[5];
    const float* b_mod   = (const float*)d_in[6];
    const float* w_reg   = (const float*)d_in[7];
    float* out = (float*)d_out;

    k_transpose<<<dim3(HW / 32, Bn), 256>>>(frame_j);
    k_w2<<<(KK * 4096 + 255) / 256, 256>>>(w_reg);
    k_wc<<<(CIN2 * 27 * 12 + 255) / 256, 256>>>(w_off, w_mod);
    k_conv<<<dim3(Ww / 32, Hh / 8, Bn * 2), 256>>>(frame_i, frame_j, flow_ij);
    k_post<<<(Bn * HW) / 256, 256>>>(b_off, b_mod);
    k_deform<<<dim3(HW / PBLK, Bn), 256>>>(out);
}

// round 7
// speedup vs baseline: 1.5601x; 1.0711x over previous
#include <cuda_runtime.h>
#include <cstdint>
#include <math.h>

#define Hh 96
#define Ww 96
#define Bn 4
#define Cc 64
#define HW (Hh*Ww)
#define KK 9
#define CIN2 130
#define PBLK 64            // pixels per deform block
#define VPITCH 68          // s_v row pitch (bank pad)
#define NST 33             // conv pipeline stages (2 cin each, 65 cins/half)

// Scratch (device globals)
__device__ float g_offset[Bn*18*HW];
__device__ float g_mod[Bn*9*HW];
__device__ float g_fjt[Bn*HW*Cc];      // frame_j as [B,HW,C]
__device__ float g_w2[KK*16*64*4];     // w_reg as [tap][chquad][o][e]
__device__ float g_wc[CIN2*27*12];     // conv weights as [cin][oc*12+kk], kk>=9 zero
__device__ float g_part[8*27*HW];      // conv partials [b*2+half][27][HW]

// ---------------------------------------------------------------------------
__device__ __forceinline__ void cpa4(unsigned int dst, const void* src, bool pred) {
    int sz = pred ? 4 : 0;
    asm volatile("cp.async.ca.shared.global [%0], [%1], 4, %2;\n"
                 :: "r"(dst), "l"(src), "r"(sz));
}
__device__ __forceinline__ void cpa_commit() {
    asm volatile("cp.async.commit_group;\n");
}
__device__ __forceinline__ unsigned long long ffma2(
    unsigned long long a, unsigned long long b, unsigned long long c) {
    unsigned long long d;
    asm("fma.rn.f32x2 %0, %1, %2, %3;" : "=l"(d) : "l"(a), "l"(b), "l"(c));
    return d;
}
__device__ __forceinline__ unsigned long long pack2(float lo, float hi) {
    unsigned long long d;
    asm("mov.b64 %0, {%1, %2};" : "=l"(d) : "f"(lo), "f"(hi));
    return d;
}
__device__ __forceinline__ float2 unpack2(unsigned long long v) {
    float lo, hi;
    asm("mov.b64 {%0, %1}, %2;" : "=f"(lo), "=f"(hi) : "l"(v));
    return make_float2(lo, hi);
}

// ---------------------------------------------------------------------------
// frame_j [B,C,H,W] -> [B,HW,C]
// ---------------------------------------------------------------------------
__global__ void k_transpose(const float* __restrict__ fj) {
    __shared__ float s[64][33];
    int b   = blockIdx.y;
    int hw0 = blockIdx.x * 32;
    int tid = threadIdx.x;
    int tx = tid & 31, ty = tid >> 5;
#pragma unroll
    for (int i = 0; i < 8; i++) {
        int c = ty + i * 8;
        s[c][tx] = fj[(size_t)(b * Cc + c) * HW + hw0 + tx];
    }
    __syncthreads();
    int ci = tid & 63, j4 = tid >> 6;
#pragma unroll
    for (int i = 0; i < 8; i++) {
        int j = j4 + i * 4;
        g_fjt[(size_t)(b * HW + hw0 + j) * Cc + ci] = s[ci][j];
    }
}

// ---------------------------------------------------------------------------
// w_reg [O=64,C=64,9] -> g_w2[tap][q][o][e] = w_reg[o][4q+e][tap]
// ---------------------------------------------------------------------------
__global__ void k_w2(const float* __restrict__ w_reg) {
    int i = blockIdx.x * 256 + threadIdx.x;
    if (i < KK * 4096) {
        int tap = i >> 12;
        int r   = i & 4095;
        int q   = r >> 8;
        int r2  = r & 255;
        int o   = r2 >> 2;
        int e   = r2 & 3;
        g_w2[i] = w_reg[(o * 64 + q * 4 + e) * KK + tap];
    }
}

// ---------------------------------------------------------------------------
// Conv weights -> g_wc[cin][oc*12+kk]  (rows padded 9->12, tail zero)
// ---------------------------------------------------------------------------
__global__ void k_wc(const float* __restrict__ w_off,
                     const float* __restrict__ w_mod) {
    int i = blockIdx.x * 256 + threadIdx.x;
    if (i < CIN2 * 27 * 12) {
        int cin = i / (27 * 12);
        int r   = i % (27 * 12);
        int oc  = r / 12, kk = r % 12;
        float v = 0.f;
        if (kk < 9)
            v = (oc < 18) ? w_off[(oc * CIN2 + cin) * 9 + kk]
                          : w_mod[((oc - 18) * CIN2 + cin) * 9 + kk];
        g_wc[i] = v;
    }
}

// ---------------------------------------------------------------------------
// Fused 3x3 conv (half of cin reduction per block), packed f32x2 FMA.
// 32x8 tile, 256 threads. Warp w: oc-group (w>>2), pixel rows (w&3, (w&3)+4).
// Weight broadcast LDS amortized over 2 pixels; 14/13 ocs per warp group.
// ---------------------------------------------------------------------------
__global__ void __launch_bounds__(256, 2) k_conv(
    const float* __restrict__ fi, const float* __restrict__ fj,
    const float* __restrict__ fl)
{
    __shared__ __align__(16) float s_in[3][2][340];
    __shared__ __align__(16) float s_w[3][2][324];
    int z  = blockIdx.z;
    int b  = z >> 1, half = z & 1;
    int cin_base = half * 65;
    int x0 = blockIdx.x * 32, y0 = blockIdx.y * 8;
    int tid = threadIdx.x;
    int tx   = tid & 31;
    int warp = tid >> 5;
    int ocg  = warp >> 2;            // 0 or 1
    int wrow = warp & 3;             // pixel rows wrow, wrow+4
    int obase = ocg ? 14 : 0;
    int noc   = ocg ? 13 : 14;

    auto stage = [&](int s, int buf) {
#pragma unroll
        for (int c2 = 0; c2 < 2; c2++) {
            int lc = s * 2 + c2;
            bool vcin = (lc < 65);
            int cin = cin_base + (vcin ? lc : 0);
            const float* src = (cin < 64)  ? fi + (size_t)(b * 64 + cin) * HW
                             : (cin < 128) ? fj + (size_t)(b * 64 + cin - 64) * HW
                                           : fl + (size_t)(b * 2 + cin - 128) * HW;
            for (int i = tid; i < 340; i += 256) {
                int ly = i / 34, lx = i % 34;
                int gy = y0 + ly - 1, gx = x0 + lx - 1;
                bool ok = vcin && (gy >= 0 && gy < Hh && gx >= 0 && gx < Ww);
                const float* g = src + (ok ? (gy * Ww + gx) : 0);
                cpa4((unsigned int)__cvta_generic_to_shared(&s_in[buf][c2][i]), g, ok);
            }
            const float* wsrc = g_wc + (size_t)cin * 324;
            for (int i = tid; i < 324; i += 256)
                cpa4((unsigned int)__cvta_generic_to_shared(&s_w[buf][c2][i]),
                     wsrc + i, vcin);
        }
    };

    unsigned long long acc2[14][2];
#pragma unroll
    for (int oc = 0; oc < 14; oc++) { acc2[oc][0] = 0ull; acc2[oc][1] = 0ull; }

    stage(0, 0); cpa_commit();
    stage(1, 1); cpa_commit();

    for (int s = 0; s < NST; s++) {
        if (s < NST - 1) asm volatile("cp.async.wait_group 1;\n");
        else             asm volatile("cp.async.wait_group 0;\n");
        __syncthreads();
        int buf = s % 3;
#pragma unroll
        for (int c2 = 0; c2 < 2; c2++) {
            const float* sb = s_in[buf][c2];
            // pixel row A = wrow, pixel row B = wrow+4
            unsigned long long vA[5], vB[5];
#pragma unroll
            for (int pr = 0; pr < 2; pr++) {
                int r = wrow + pr * 4;
                float t0 = sb[(r + 0) * 34 + tx + 0];
                float t1 = sb[(r + 0) * 34 + tx + 1];
                float t2 = sb[(r + 0) * 34 + tx + 2];
                float t3 = sb[(r + 1) * 34 + tx + 0];
                float t4 = sb[(r + 1) * 34 + tx + 1];
                float t5 = sb[(r + 1) * 34 + tx + 2];
                float t6 = sb[(r + 2) * 34 + tx + 0];
                float t7 = sb[(r + 2) * 34 + tx + 1];
                float t8 = sb[(r + 2) * 34 + tx + 2];
                unsigned long long* v = pr ? vB : vA;
                v[0] = pack2(t0, t1);
                v[1] = pack2(t2, t3);
                v[2] = pack2(t4, t5);
                v[3] = pack2(t6, t7);
                v[4] = pack2(t8, 0.f);
            }
#pragma unroll
            for (int oi = 0; oi < 14; oi++) {
                if (oi < noc) {
                    const float* wr = &s_w[buf][c2][(obase + oi) * 12];
                    ulonglong2 wab = *(const ulonglong2*)wr;
                    ulonglong2 wcd = *(const ulonglong2*)(wr + 4);
                    unsigned long long w89 = *(const unsigned long long*)(wr + 8);
                    unsigned long long a = acc2[oi][0];
                    a = ffma2(vA[0], wab.x, a);
                    a = ffma2(vA[1], wab.y, a);
                    a = ffma2(vA[2], wcd.x, a);
                    a = ffma2(vA[3], wcd.y, a);
                    a = ffma2(vA[4], w89, a);
                    acc2[oi][0] = a;
                    unsigned long long c = acc2[oi][1];
                    c = ffma2(vB[0], wab.x, c);
                    c = ffma2(vB[1], wab.y, c);
                    c = ffma2(vB[2], wcd.x, c);
                    c = ffma2(vB[3], wcd.y, c);
                    c = ffma2(vB[4], w89, c);
                    acc2[oi][1] = c;
                }
            }
        }
        if (s + 2 < NST) { stage(s + 2, (s + 2) % 3); cpa_commit(); }
    }

    int pA = (y0 + wrow) * Ww + x0 + tx;
    int pB = pA + 4 * Ww;
#pragma unroll
    for (int oi = 0; oi < 14; oi++) {
        if (oi < noc) {
            float* dst = g_part + ((size_t)z * 27 + obase + oi) * HW;
            float2 uA = unpack2(acc2[oi][0]);
            float2 uB = unpack2(acc2[oi][1]);
            dst[pA] = uA.x + uA.y;
            dst[pB] = uB.x + uB.y;
        }
    }
}

// ---------------------------------------------------------------------------
// Combine conv halves + bias (+ 2*sigmoid for modulator)
// ---------------------------------------------------------------------------
__global__ void k_post(const float* __restrict__ b_off,
                       const float* __restrict__ b_mod) {
    int t = blockIdx.x * 256 + threadIdx.x;   // 0 .. Bn*HW-1
    int b = t / HW, p = t % HW;
    const float* p0 = g_part + ((size_t)(b * 2)     * 27) * HW + p;
    const float* p1 = g_part + ((size_t)(b * 2 + 1) * 27) * HW + p;
#pragma unroll
    for (int oc = 0; oc < 18; oc++)
        g_offset[(size_t)(b * 18 + oc) * HW + p] =
            p0[oc * HW] + p1[oc * HW] + b_off[oc];
#pragma unroll
    for (int mc = 0; mc < 9; mc++) {
        float zz = p0[(18 + mc) * HW] + p1[(18 + mc) * HW] + b_mod[mc];
        g_mod[(size_t)(b * 9 + mc) * HW + p] = 2.f / (1.f + expf(-zz));
    }
}

// ---------------------------------------------------------------------------
// Deformable conv: block = 64 pixels x 64 outputs, 256 threads.
// Contract uses packed f32x2 FMA (even/odd channel partials).
// ---------------------------------------------------------------------------
__global__ void __launch_bounds__(256, 3) k_deform(float* __restrict__ out) {
    __shared__ __align__(16) float s_v[PBLK * VPITCH];
    __shared__ __align__(16) float s_w[4096];
    __shared__ float          s_cw[PBLK * 9][4];
    __shared__ unsigned short s_ci[PBLK * 9][4];

    int b   = blockIdx.y;
    int p0  = blockIdx.x * PBLK;
    int tid = threadIdx.x;

    for (int i = tid; i < PBLK * 9; i += 256) {
        int pix = i / 9, tap = i % 9;
        int p = p0 + pix;
        int y = p / Ww, x = p % Ww;
        int ky = tap / 3, kx = tap % 3;
        float offy = g_offset[(size_t)(b * 18 + 2 * tap)     * HW + p];
        float offx = g_offset[(size_t)(b * 18 + 2 * tap + 1) * HW + p];
        float m    = g_mod   [(size_t)(b * 9  + tap)         * HW + p];
        float py = (float)(y - 1 + ky) + offy;
        float px = (float)(x - 1 + kx) + offx;
        float fy = floorf(py), fx = floorf(px);
        int y0i = (int)fy, x0i = (int)fx;
        float wy = py - fy, wx = px - fx;
#pragma unroll
        for (int d = 0; d < 4; d++) {
            int dy = d >> 1, dx = d & 1;
            int yc = y0i + dy, xc = x0i + dx;
            bool ok = (yc >= 0) && (yc < Hh) && (xc >= 0) && (xc < Ww);
            float w = (dy ? wy : 1.f - wy) * (dx ? wx : 1.f - wx) * m;
            s_cw[i][d] = ok ? w : 0.f;
            int ycc = min(max(yc, 0), Hh - 1);
            int xcc = min(max(xc, 0), Ww - 1);
            s_ci[i][d] = (unsigned short)(ycc * Ww + xcc);
        }
    }

    unsigned long long a2[16];
#pragma unroll
    for (int oi = 0; oi < 16; oi++) a2[oi] = 0ull;

    int lane = tid & 31;
    int o0   = (tid >> 5) * 8;
    int gp   = tid >> 3;
    int gq   = tid & 7;
    const float* fb = g_fjt + (size_t)b * HW * Cc;

    __syncthreads();

    for (int tap = 0; tap < 9; tap++) {
        {
            const float4* src = (const float4*)(g_w2 + tap * 4096);
            float4* dst = (float4*)s_w;
#pragma unroll
            for (int i = 0; i < 4; i++)
                dst[tid + i * 256] = src[tid + i * 256];
        }
#pragma unroll
        for (int ph = 0; ph < 2; ph++) {
            int pix = gp + 32 * ph;
            int j = pix * 9 + tap;
            float w0 = s_cw[j][0], w1 = s_cw[j][1];
            float w2 = s_cw[j][2], w3 = s_cw[j][3];
            const float* pp0 = fb + (size_t)s_ci[j][0] * Cc;
            const float* pp1 = fb + (size_t)s_ci[j][1] * Cc;
            const float* pp2 = fb + (size_t)s_ci[j][2] * Cc;
            const float* pp3 = fb + (size_t)s_ci[j][3] * Cc;
#pragma unroll
            for (int qq = 0; qq < 2; qq++) {
                int q = gq + qq * 8;
                float4 f0 = *(const float4*)(pp0 + q * 4);
                float4 f1 = *(const float4*)(pp1 + q * 4);
                float4 f2 = *(const float4*)(pp2 + q * 4);
                float4 f3 = *(const float4*)(pp3 + q * 4);
                float4 v;
                v.x = w0 * f0.x + w1 * f1.x + w2 * f2.x + w3 * f3.x;
                v.y = w0 * f0.y + w1 * f1.y + w2 * f2.y + w3 * f3.y;
                v.z = w0 * f0.z + w1 * f1.z + w2 * f2.z + w3 * f3.z;
                v.w = w0 * f0.w + w1 * f1.w + w2 * f2.w + w3 * f3.w;
                *(float4*)(s_v + pix * VPITCH + q * 4) = v;
            }
        }
        __syncthreads();

        {
            const float* va = s_v + lane * VPITCH;
            const float* vb = s_v + (lane + 32) * VPITCH;
#pragma unroll 4
            for (int q = 0; q < 16; q++) {
                ulonglong2 ta = *(const ulonglong2*)(va + q * 4);
                ulonglong2 tb = *(const ulonglong2*)(vb + q * 4);
#pragma unroll
                for (int oi = 0; oi < 8; oi++) {
                    ulonglong2 wv = *(const ulonglong2*)(s_w + (q * 64 + o0 + oi) * 4);
                    unsigned long long x = a2[oi];
                    x = ffma2(ta.x, wv.x, x);
                    x = ffma2(ta.y, wv.y, x);
                    a2[oi] = x;
                    unsigned long long y2 = a2[8 + oi];
                    y2 = ffma2(tb.x, wv.x, y2);
                    y2 = ffma2(tb.y, wv.y, y2);
                    a2[8 + oi] = y2;
                }
            }
        }
        __syncthreads();
    }

#pragma unroll
    for (int oi = 0; oi < 8; oi++) {
        size_t base = (size_t)(b * 64 + o0 + oi) * HW + p0;
        float2 ua = unpack2(a2[oi]);
        float2 ub = unpack2(a2[8 + oi]);
        out[base + lane]      = ua.x + ua.y;
        out[base + 32 + lane] = ub.x + ub.y;
    }
}

// ---------------------------------------------------------------------------
extern "C" void kernel_launch(void* const* d_in, const int* in_sizes, int n_in,
                              void* d_out, int out_size) {
    const float* frame_i = (const float*)d_in[0];
    const float* frame_j = (const float*)d_in[1];
    const float* flow_ij = (const float*)d_in[2];
    const float* w_off   = (const float*)d_in[3];
    const float* b_off   = (const float*)d_in[4];
    const float* w_mod   = (const float*)d_in[5];
    const float* b_mod   = (const float*)d_in[6];
    const float* w_reg   = (const float*)d_in[7];
    float* out = (float*)d_out;

    k_transpose<<<dim3(HW / 32, Bn), 256>>>(frame_j);
    k_w2<<<(KK * 4096 + 255) / 256, 256>>>(w_reg);
    k_wc<<<(CIN2 * 27 * 12 + 255) / 256, 256>>>(w_off, w_mod);
    k_conv<<<dim3(Ww / 32, Hh / 8, Bn * 2), 256>>>(frame_i, frame_j, flow_ij);
    k_post<<<(Bn * HW) / 256, 256>>>(b_off, b_mod);
    k_deform<<<dim3(HW / PBLK, Bn), 256>>>(out);
}

// round 8
// speedup vs baseline: 1.6585x; 1.0631x over previous
#include <cuda_runtime.h>
#include <cstdint>
#include <math.h>

#define Hh 96
#define Ww 96
#define Bn 4
#define Cc 64
#define HW (Hh*Ww)
#define KK 9
#define CIN2 130
#define PBLK 64            // pixels per deform block
#define VPITCH 68          // s_v row pitch (bank pad)
#define NST 33             // conv pipeline stages (2 cin each, 65 cins/half)

// Scratch (device globals)
__device__ float g_fjt[Bn*HW*Cc];      // frame_j as [B,HW,C]
__device__ float g_w2[KK*16*64*4];     // w_reg as [tap][chquad][o][e]
__device__ float g_wc[CIN2*27*12];     // conv weights as [cin][oc*12+kk], kk>=9 zero
__device__ float g_part[8*27*HW];      // conv partials [b*2+half][27][HW]

// ---------------------------------------------------------------------------
__device__ __forceinline__ void cpa4(unsigned int dst, const void* src, bool pred) {
    int sz = pred ? 4 : 0;
    asm volatile("cp.async.ca.shared.global [%0], [%1], 4, %2;\n"
                 :: "r"(dst), "l"(src), "r"(sz));
}
__device__ __forceinline__ void cpa_commit() {
    asm volatile("cp.async.commit_group;\n");
}
__device__ __forceinline__ unsigned long long ffma2(
    unsigned long long a, unsigned long long b, unsigned long long c) {
    unsigned long long d;
    asm("fma.rn.f32x2 %0, %1, %2, %3;" : "=l"(d) : "l"(a), "l"(b), "l"(c));
    return d;
}
__device__ __forceinline__ unsigned long long pack2(float lo, float hi) {
    unsigned long long d;
    asm("mov.b64 %0, {%1, %2};" : "=l"(d) : "f"(lo), "f"(hi));
    return d;
}
__device__ __forceinline__ float2 unpack2(unsigned long long v) {
    float lo, hi;
    asm("mov.b64 {%0, %1}, %2;" : "=f"(lo), "=f"(hi) : "l"(v));
    return make_float2(lo, hi);
}

// ---------------------------------------------------------------------------
// frame_j [B,C,H,W] -> [B,HW,C]
// ---------------------------------------------------------------------------
__global__ void k_transpose(const float* __restrict__ fj) {
    __shared__ float s[64][33];
    int b   = blockIdx.y;
    int hw0 = blockIdx.x * 32;
    int tid = threadIdx.x;
    int tx = tid & 31, ty = tid >> 5;
#pragma unroll
    for (int i = 0; i < 8; i++) {
        int c = ty + i * 8;
        s[c][tx] = fj[(size_t)(b * Cc + c) * HW + hw0 + tx];
    }
    __syncthreads();
    int ci = tid & 63, j4 = tid >> 6;
#pragma unroll
    for (int i = 0; i < 8; i++) {
        int j = j4 + i * 4;
        g_fjt[(size_t)(b * HW + hw0 + j) * Cc + ci] = s[ci][j];
    }
}

// ---------------------------------------------------------------------------
// w_reg [O=64,C=64,9] -> g_w2[tap][q][o][e] = w_reg[o][4q+e][tap]
// ---------------------------------------------------------------------------
__global__ void k_w2(const float* __restrict__ w_reg) {
    int i = blockIdx.x * 256 + threadIdx.x;
    if (i < KK * 4096) {
        int tap = i >> 12;
        int r   = i & 4095;
        int q   = r >> 8;
        int r2  = r & 255;
        int o   = r2 >> 2;
        int e   = r2 & 3;
        g_w2[i] = w_reg[(o * 64 + q * 4 + e) * KK + tap];
    }
}

// ---------------------------------------------------------------------------
// Conv weights -> g_wc[cin][oc*12+kk]  (rows padded 9->12, tail zero)
// ---------------------------------------------------------------------------
__global__ void k_wc(const float* __restrict__ w_off,
                     const float* __restrict__ w_mod) {
    int i = blockIdx.x * 256 + threadIdx.x;
    if (i < CIN2 * 27 * 12) {
        int cin = i / (27 * 12);
        int r   = i % (27 * 12);
        int oc  = r / 12, kk = r % 12;
        float v = 0.f;
        if (kk < 9)
            v = (oc < 18) ? w_off[(oc * CIN2 + cin) * 9 + kk]
                          : w_mod[((oc - 18) * CIN2 + cin) * 9 + kk];
        g_wc[i] = v;
    }
}

// ---------------------------------------------------------------------------
// Fused 3x3 conv (half of cin reduction per block), packed f32x2 FMA.
// 32x8 tile, 256 threads. warp w: oc-group (w>>1, 7 ocs), rows 4*(w&1)+0..3.
// All staging addresses hoisted out of the pipeline loop.
// ---------------------------------------------------------------------------
__global__ void __launch_bounds__(256, 2) k_conv(
    const float* __restrict__ fi, const float* __restrict__ fj,
    const float* __restrict__ fl)
{
    __shared__ __align__(16) float s_in[3][2][340];
    __shared__ __align__(16) float s_w[3][2][324];
    int z  = blockIdx.z;
    int b  = z >> 1, half = z & 1;
    int cin_base = half * 65;
    int x0 = blockIdx.x * 32, y0 = blockIdx.y * 8;
    int tid = threadIdx.x;
    int tx   = tid & 31;
    int warp = tid >> 5;
    int ocg  = warp >> 1;            // 0..3
    int wrow = (warp & 1) * 4;       // pixel rows wrow..wrow+3
    int obase = ocg * 7;
    int noc   = (ocg == 3) ? 6 : 7;

    // ---- hoisted staging geometry (tid-invariant across stages) ----
    // input tile: 340 elems, thread covers i0=tid and i1=tid+256 (if tid<84)
    int ily0 = tid / 34,        ilx0 = tid % 34;
    int i1   = tid + 256;
    int ily1 = i1 / 34,         ilx1 = i1 % 34;
    int gy0 = y0 + ily0 - 1, gx0 = x0 + ilx0 - 1;
    int gy1 = y0 + ily1 - 1, gx1 = x0 + ilx1 - 1;
    bool sok0 = (gy0 >= 0 && gy0 < Hh && gx0 >= 0 && gx0 < Ww);
    bool sok1 = (tid < 84) && (gy1 >= 0 && gy1 < Hh && gx1 >= 0 && gx1 < Ww);
    int soff0 = sok0 ? (gy0 * Ww + gx0) : 0;
    int soff1 = sok1 ? (gy1 * Ww + gx1) : 0;
    bool wok1 = (tid < 68);          // weights: 324 elems

    auto stage = [&](int s, int buf) {
#pragma unroll
        for (int c2 = 0; c2 < 2; c2++) {
            int lc = s * 2 + c2;
            bool vcin = (lc < 65);
            int cin = cin_base + (vcin ? lc : 0);
            const float* src = (cin < 64)  ? fi + (size_t)(b * 64 + cin) * HW
                             : (cin < 128) ? fj + (size_t)(b * 64 + cin - 64) * HW
                                           : fl + (size_t)(b * 2 + cin - 128) * HW;
            float* din = s_in[buf][c2];
            cpa4((unsigned int)__cvta_generic_to_shared(din + tid),
                 src + soff0, vcin && sok0);
            if (tid < 84)
                cpa4((unsigned int)__cvta_generic_to_shared(din + tid + 256),
                     src + soff1, vcin && sok1);
            const float* wsrc = g_wc + (size_t)cin * 324;
            float* dw = s_w[buf][c2];
            cpa4((unsigned int)__cvta_generic_to_shared(dw + tid),
                 wsrc + tid, vcin);
            if (wok1)
                cpa4((unsigned int)__cvta_generic_to_shared(dw + tid + 256),
                     wsrc + tid + 256, vcin);
        }
    };

    unsigned long long acc2[7][4];
#pragma unroll
    for (int oi = 0; oi < 7; oi++)
#pragma unroll
        for (int px = 0; px < 4; px++) acc2[oi][px] = 0ull;

    stage(0, 0); cpa_commit();
    stage(1, 1); cpa_commit();

    for (int s = 0; s < NST; s++) {
        if (s < NST - 1) asm volatile("cp.async.wait_group 1;\n");
        else             asm volatile("cp.async.wait_group 0;\n");
        __syncthreads();
        int buf = s % 3;
#pragma unroll
        for (int c2 = 0; c2 < 2; c2++) {
            const float* sb = s_in[buf][c2] + wrow * 34 + tx;
            float t[6][3];
#pragma unroll
            for (int jr = 0; jr < 6; jr++)
#pragma unroll
                for (int jc = 0; jc < 3; jc++)
                    t[jr][jc] = sb[jr * 34 + jc];
            unsigned long long v[4][5];
#pragma unroll
            for (int px = 0; px < 4; px++) {
                v[px][0] = pack2(t[px][0],     t[px][1]);
                v[px][1] = pack2(t[px][2],     t[px + 1][0]);
                v[px][2] = pack2(t[px + 1][1], t[px + 1][2]);
                v[px][3] = pack2(t[px + 2][0], t[px + 2][1]);
                v[px][4] = pack2(t[px + 2][2], 0.f);
            }
#pragma unroll
            for (int oi = 0; oi < 7; oi++) {
                if (oi < noc) {
                    const float* wr = &s_w[buf][c2][(obase + oi) * 12];
                    ulonglong2 wab = *(const ulonglong2*)wr;
                    ulonglong2 wcd = *(const ulonglong2*)(wr + 4);
                    unsigned long long w89 = *(const unsigned long long*)(wr + 8);
#pragma unroll
                    for (int px = 0; px < 4; px++) {
                        unsigned long long a = acc2[oi][px];
                        a = ffma2(v[px][0], wab.x, a);
                        a = ffma2(v[px][1], wab.y, a);
                        a = ffma2(v[px][2], wcd.x, a);
                        a = ffma2(v[px][3], wcd.y, a);
                        a = ffma2(v[px][4], w89, a);
                        acc2[oi][px] = a;
                    }
                }
            }
        }
        if (s + 2 < NST) { stage(s + 2, (s + 2) % 3); cpa_commit(); }
    }

#pragma unroll
    for (int oi = 0; oi < 7; oi++) {
        if (oi < noc) {
            float* dst = g_part + ((size_t)z * 27 + obase + oi) * HW;
#pragma unroll
            for (int px = 0; px < 4; px++) {
                float2 u = unpack2(acc2[oi][px]);
                dst[(y0 + wrow + px) * Ww + x0 + tx] = u.x + u.y;
            }
        }
    }
}

// ---------------------------------------------------------------------------
// Deformable conv: block = 64 pixels x 64 outputs, 256 threads.
// Phase 1 fuses the conv-partial combine + bias + 2*sigmoid.
// ---------------------------------------------------------------------------
__global__ void __launch_bounds__(256, 3) k_deform(
    float* __restrict__ out,
    const float* __restrict__ b_off, const float* __restrict__ b_mod)
{
    __shared__ __align__(16) float s_v[PBLK * VPITCH];
    __shared__ __align__(16) float s_w[4096];
    __shared__ float          s_cw[PBLK * 9][4];
    __shared__ unsigned short s_ci[PBLK * 9][4];

    int b   = blockIdx.y;
    int p0  = blockIdx.x * PBLK;
    int tid = threadIdx.x;

    const float* P0 = g_part + (size_t)(b * 2)     * 27 * HW;
    const float* P1 = g_part + (size_t)(b * 2 + 1) * 27 * HW;

    for (int i = tid; i < PBLK * 9; i += 256) {
        int pix = i / 9, tap = i % 9;
        int p = p0 + pix;
        int y = p / Ww, x = p % Ww;
        int ky = tap / 3, kx = tap % 3;
        float offy = P0[(2 * tap)     * HW + p] + P1[(2 * tap)     * HW + p]
                   + b_off[2 * tap];
        float offx = P0[(2 * tap + 1) * HW + p] + P1[(2 * tap + 1) * HW + p]
                   + b_off[2 * tap + 1];
        float zz   = P0[(18 + tap)    * HW + p] + P1[(18 + tap)    * HW + p]
                   + b_mod[tap];
        float m = 2.f / (1.f + expf(-zz));
        float py = (float)(y - 1 + ky) + offy;
        float px = (float)(x - 1 + kx) + offx;
        float fy = floorf(py), fx = floorf(px);
        int y0i = (int)fy, x0i = (int)fx;
        float wy = py - fy, wx = px - fx;
#pragma unroll
        for (int d = 0; d < 4; d++) {
            int dy = d >> 1, dx = d & 1;
            int yc = y0i + dy, xc = x0i + dx;
            bool ok = (yc >= 0) && (yc < Hh) && (xc >= 0) && (xc < Ww);
            float w = (dy ? wy : 1.f - wy) * (dx ? wx : 1.f - wx) * m;
            s_cw[i][d] = ok ? w : 0.f;
            int ycc = min(max(yc, 0), Hh - 1);
            int xcc = min(max(xc, 0), Ww - 1);
            s_ci[i][d] = (unsigned short)(ycc * Ww + xcc);
        }
    }

    unsigned long long a2[16];
#pragma unroll
    for (int oi = 0; oi < 16; oi++) a2[oi] = 0ull;

    int lane = tid & 31;
    int o0   = (tid >> 5) * 8;
    int gp   = tid >> 3;
    int gq   = tid & 7;
    const float* fb = g_fjt + (size_t)b * HW * Cc;

    __syncthreads();

    for (int tap = 0; tap < 9; tap++) {
        {
            const float4* src = (const float4*)(g_w2 + tap * 4096);
            float4* dst = (float4*)s_w;
#pragma unroll
            for (int i = 0; i < 4; i++)
                dst[tid + i * 256] = src[tid + i * 256];
        }
#pragma unroll
        for (int ph = 0; ph < 2; ph++) {
            int pix = gp + 32 * ph;
            int j = pix * 9 + tap;
            float w0 = s_cw[j][0], w1 = s_cw[j][1];
            float w2 = s_cw[j][2], w3 = s_cw[j][3];
            const float* pp0 = fb + (size_t)s_ci[j][0] * Cc;
            const float* pp1 = fb + (size_t)s_ci[j][1] * Cc;
            const float* pp2 = fb + (size_t)s_ci[j][2] * Cc;
            const float* pp3 = fb + (size_t)s_ci[j][3] * Cc;
#pragma unroll
            for (int qq = 0; qq < 2; qq++) {
                int q = gq + qq * 8;
                float4 f0 = *(const float4*)(pp0 + q * 4);
                float4 f1 = *(const float4*)(pp1 + q * 4);
                float4 f2 = *(const float4*)(pp2 + q * 4);
                float4 f3 = *(const float4*)(pp3 + q * 4);
                float4 v;
                v.x = w0 * f0.x + w1 * f1.x + w2 * f2.x + w3 * f3.x;
                v.y = w0 * f0.y + w1 * f1.y + w2 * f2.y + w3 * f3.y;
                v.z = w0 * f0.z + w1 * f1.z + w2 * f2.z + w3 * f3.z;
                v.w = w0 * f0.w + w1 * f1.w + w2 * f2.w + w3 * f3.w;
                *(float4*)(s_v + pix * VPITCH + q * 4) = v;
            }
        }
        __syncthreads();

        {
            const float* va = s_v + lane * VPITCH;
            const float* vb = s_v + (lane + 32) * VPITCH;
#pragma unroll 4
            for (int q = 0; q < 16; q++) {
                ulonglong2 ta = *(const ulonglong2*)(va + q * 4);
                ulonglong2 tb = *(const ulonglong2*)(vb + q * 4);
#pragma unroll
                for (int oi = 0; oi < 8; oi++) {
                    ulonglong2 wv = *(const ulonglong2*)(s_w + (q * 64 + o0 + oi) * 4);
                    unsigned long long x = a2[oi];
                    x = ffma2(ta.x, wv.x, x);
                    x = ffma2(ta.y, wv.y, x);
                    a2[oi] = x;
                    unsigned long long y2 = a2[8 + oi];
                    y2 = ffma2(tb.x, wv.x, y2);
                    y2 = ffma2(tb.y, wv.y, y2);
                    a2[8 + oi] = y2;
                }
            }
        }
        __syncthreads();
    }

#pragma unroll
    for (int oi = 0; oi < 8; oi++) {
        size_t base = (size_t)(b * 64 + o0 + oi) * HW + p0;
        float2 ua = unpack2(a2[oi]);
        float2 ub = unpack2(a2[8 + oi]);
        out[base + lane]      = ua.x + ua.y;
        out[base + 32 + lane] = ub.x + ub.y;
    }
}

// ---------------------------------------------------------------------------
extern "C" void kernel_launch(void* const* d_in, const int* in_sizes, int n_in,
                              void* d_out, int out_size) {
    const float* frame_i = (const float*)d_in[0];
    const float* frame_j = (const float*)d_in[1];
    const float* flow_ij = (const float*)d_in[2];
    const float* w_off   = (const float*)d_in[3];
    const float* b_off   = (const float*)d_in[4];
    const float* w_mod   = (const float*)d_in[5];
    const float* b_mod   = (const float*)d_in[6];
    const float* w_reg   = (const float*)d_in[7];
    float* out = (float*)d_out;

    k_transpose<<<dim3(HW / 32, Bn), 256>>>(frame_j);
    k_w2<<<(KK * 4096 + 255) / 256, 256>>>(w_reg);
    k_wc<<<(CIN2 * 27 * 12 + 255) / 256, 256>>>(w_off, w_mod);
    k_conv<<<dim3(Ww / 32, Hh / 8, Bn * 2), 256>>>(frame_i, frame_j, flow_ij);
    k_deform<<<dim3(HW / PBLK, Bn), 256>>>(out, b_off, b_mod);
}

// round 9
// speedup vs baseline: 1.8733x; 1.1295x over previous
#include <cuda_runtime.h>
#include <cstdint>
#include <math.h>

#define Hh 96
#define Ww 96
#define Bn 4
#define Cc 64
#define HW (Hh*Ww)
#define KK 9
#define CIN2 130
#define PBLK 64            // pixels per deform block
#define VPITCH 68          // s_v row pitch (bank pad)
#define NPAIR 33           // conv pipeline stages per half (1 cin-pair each)

// Scratch (device globals)
__device__ float g_fjt[Bn*HW*Cc];      // frame_j as [B,HW,C]
__device__ float g_w2[KK*16*64*4];     // w_reg as [tap][chquad][o][e]
__device__ float g_wc2[66*28*20];      // conv w: [cinpair][oc(28)][tap(10)][c(2)]
__device__ float g_part[8*28*HW];      // conv partials [b*2+half][28][HW]

// ---------------------------------------------------------------------------
__device__ __forceinline__ void cpa4(unsigned int dst, const void* src, bool pred) {
    int sz = pred ? 4 : 0;
    asm volatile("cp.async.ca.shared.global [%0], [%1], 4, %2;\n"
                 :: "r"(dst), "l"(src), "r"(sz));
}
__device__ __forceinline__ void cpa_commit() {
    asm volatile("cp.async.commit_group;\n");
}
__device__ __forceinline__ unsigned long long ffma2(
    unsigned long long a, unsigned long long b, unsigned long long c) {
    unsigned long long d;
    asm("fma.rn.f32x2 %0, %1, %2, %3;" : "=l"(d) : "l"(a), "l"(b), "l"(c));
    return d;
}
__device__ __forceinline__ float2 unpack2(unsigned long long v) {
    float lo, hi;
    asm("mov.b64 {%0, %1}, %2;" : "=f"(lo), "=f"(hi) : "l"(v));
    return make_float2(lo, hi);
}

// ---------------------------------------------------------------------------
// frame_j [B,C,H,W] -> [B,HW,C]
// ---------------------------------------------------------------------------
__global__ void k_transpose(const float* __restrict__ fj) {
    __shared__ float s[64][33];
    int b   = blockIdx.y;
    int hw0 = blockIdx.x * 32;
    int tid = threadIdx.x;
    int tx = tid & 31, ty = tid >> 5;
#pragma unroll
    for (int i = 0; i < 8; i++) {
        int c = ty + i * 8;
        s[c][tx] = fj[(size_t)(b * Cc + c) * HW + hw0 + tx];
    }
    __syncthreads();
    int ci = tid & 63, j4 = tid >> 6;
#pragma unroll
    for (int i = 0; i < 8; i++) {
        int j = j4 + i * 4;
        g_fjt[(size_t)(b * HW + hw0 + j) * Cc + ci] = s[ci][j];
    }
}

// ---------------------------------------------------------------------------
// w_reg [O=64,C=64,9] -> g_w2[tap][q][o][e] = w_reg[o][4q+e][tap]
// ---------------------------------------------------------------------------
__global__ void k_w2(const float* __restrict__ w_reg) {
    int i = blockIdx.x * 256 + threadIdx.x;
    if (i < KK * 4096) {
        int tap = i >> 12;
        int r   = i & 4095;
        int q   = r >> 8;
        int r2  = r & 255;
        int o   = r2 >> 2;
        int e   = r2 & 3;
        g_w2[i] = w_reg[(o * 64 + q * 4 + e) * KK + tap];
    }
}

// ---------------------------------------------------------------------------
// Conv weights -> g_wc2[pr][oc][tap][c] = w[2*pr+c][oc][tap]
//   oc 27 / tap 9 / cin>=130 are zero pads.
// ---------------------------------------------------------------------------
__global__ void k_wc2(const float* __restrict__ w_off,
                      const float* __restrict__ w_mod) {
    int i = blockIdx.x * 256 + threadIdx.x;
    if (i < 66 * 560) {
        int pr = i / 560;
        int r  = i % 560;
        int oc = r / 20;
        int r2 = r % 20;
        int tap = r2 >> 1, c = r2 & 1;
        int cin = 2 * pr + c;
        float v = 0.f;
        if (tap < 9 && oc < 27 && cin < CIN2)
            v = (oc < 18) ? w_off[(oc * CIN2 + cin) * 9 + tap]
                          : w_mod[((oc - 18) * CIN2 + cin) * 9 + tap];
        g_wc2[i] = v;
    }
}

// ---------------------------------------------------------------------------
// Fused 3x3 conv (half the cin reduction per block). Channel-PAIR packed
// FFMA2: shared buffers interleave the 2 channels of each stage, so every
// v operand is one aligned LDS.64 and every w operand is a broadcast pair.
// 32x8 tile, 256 threads. warp w: oc-group (w>>1, 7 ocs), rows 4*(w&1)+0..3.
// ---------------------------------------------------------------------------
__global__ void __launch_bounds__(256, 2) k_conv(
    const float* __restrict__ fi, const float* __restrict__ fj,
    const float* __restrict__ fl)
{
    __shared__ __align__(16) float s_in[3][680];   // [pix(340)][c(2)]
    __shared__ __align__(16) float s_w[3][560];    // [oc(28)][tap(10)][c(2)]
    int z  = blockIdx.z;
    int b  = z >> 1, half = z & 1;
    int pr_base = half * NPAIR;
    int x0 = blockIdx.x * 32, y0 = blockIdx.y * 8;
    int tid = threadIdx.x;
    int tx   = tid & 31;
    int warp = tid >> 5;
    int ocg  = warp >> 1;            // 0..3
    int wrow = (warp & 1) * 4;       // pixel rows wrow..wrow+3
    int obase = ocg * 7;             // ocs obase..obase+6 (oc 27 = pad)

    // hoisted staging geometry (tid-invariant)
    int ily0 = tid / 34,  ilx0 = tid % 34;
    int i1   = tid + 256;
    int ily1 = i1 / 34,   ilx1 = i1 % 34;
    int gy0 = y0 + ily0 - 1, gx0 = x0 + ilx0 - 1;
    int gy1 = y0 + ily1 - 1, gx1 = x0 + ilx1 - 1;
    bool sok0 = (gy0 >= 0 && gy0 < Hh && gx0 >= 0 && gx0 < Ww);
    bool sok1 = (tid < 84) && (gy1 >= 0 && gy1 < Hh && gx1 >= 0 && gx1 < Ww);
    int soff0 = sok0 ? (gy0 * Ww + gx0) : 0;
    int soff1 = sok1 ? (gy1 * Ww + gx1) : 0;

    auto stage = [&](int s, int buf) {
        int pr = pr_base + s;
#pragma unroll
        for (int c = 0; c < 2; c++) {
            int cin = 2 * pr + c;
            bool vc = (cin < CIN2);
            int ci2 = vc ? cin : 128;   // pad channels -> any valid src
            const float* src = (ci2 < 64)  ? fi + (size_t)(b * 64 + ci2) * HW
                             : (ci2 < 128) ? fj + (size_t)(b * 64 + ci2 - 64) * HW
                                           : fl + (size_t)(b * 2 + ci2 - 128) * HW;
            float* din = s_in[buf];
            cpa4((unsigned int)__cvta_generic_to_shared(din + tid * 2 + c),
                 src + soff0, vc && sok0);
            if (tid < 84)
                cpa4((unsigned int)__cvta_generic_to_shared(din + (tid + 256) * 2 + c),
                     src + soff1, vc && sok1);
        }
        const float* wsrc = g_wc2 + (size_t)pr * 560;
        float* dw = s_w[buf];
        cpa4((unsigned int)__cvta_generic_to_shared(dw + tid), wsrc + tid, true);
        cpa4((unsigned int)__cvta_generic_to_shared(dw + tid + 256),
             wsrc + tid + 256, true);
        if (tid < 48)
            cpa4((unsigned int)__cvta_generic_to_shared(dw + tid + 512),
                 wsrc + tid + 512, true);
    };

    unsigned long long acc2[7][4];
#pragma unroll
    for (int oi = 0; oi < 7; oi++)
#pragma unroll
        for (int px = 0; px < 4; px++) acc2[oi][px] = 0ull;

    stage(0, 0); cpa_commit();
    stage(1, 1); cpa_commit();

    for (int s = 0; s < NPAIR; s++) {
        if (s < NPAIR - 1) asm volatile("cp.async.wait_group 1;\n");
        else               asm volatile("cp.async.wait_group 0;\n");
        __syncthreads();
        int buf = s % 3;

        const float* sb = s_in[buf] + (wrow * 34 + tx) * 2;
        unsigned long long t2[6][3];
#pragma unroll
        for (int jr = 0; jr < 6; jr++)
#pragma unroll
            for (int jc = 0; jc < 3; jc++)
                t2[jr][jc] = *(const unsigned long long*)(sb + (jr * 34 + jc) * 2);

        const float* swb = s_w[buf];
#pragma unroll
        for (int oi = 0; oi < 7; oi++) {
            const float* wr = swb + (obase + oi) * 20;
            ulonglong2 wA = *(const ulonglong2*)wr;         // taps 0,1
            ulonglong2 wB = *(const ulonglong2*)(wr + 4);   // taps 2,3
            ulonglong2 wC = *(const ulonglong2*)(wr + 8);   // taps 4,5
            ulonglong2 wD = *(const ulonglong2*)(wr + 12);  // taps 6,7
            unsigned long long w8 = *(const unsigned long long*)(wr + 16); // tap 8
#pragma unroll
            for (int px = 0; px < 4; px++) {
                unsigned long long a = acc2[oi][px];
                a = ffma2(t2[px + 0][0], wA.x, a);
                a = ffma2(t2[px + 0][1], wA.y, a);
                a = ffma2(t2[px + 0][2], wB.x, a);
                a = ffma2(t2[px + 1][0], wB.y, a);
                a = ffma2(t2[px + 1][1], wC.x, a);
                a = ffma2(t2[px + 1][2], wC.y, a);
                a = ffma2(t2[px + 2][0], wD.x, a);
                a = ffma2(t2[px + 2][1], wD.y, a);
                a = ffma2(t2[px + 2][2], w8, a);
                acc2[oi][px] = a;
            }
        }
        if (s + 2 < NPAIR) { stage(s + 2, (s + 2) % 3); cpa_commit(); }
    }

#pragma unroll
    for (int oi = 0; oi < 7; oi++) {
        float* dst = g_part + ((size_t)z * 28 + obase + oi) * HW;
#pragma unroll
        for (int px = 0; px < 4; px++) {
            float2 u = unpack2(acc2[oi][px]);
            dst[(y0 + wrow + px) * Ww + x0 + tx] = u.x + u.y;
        }
    }
}

// ---------------------------------------------------------------------------
// Deformable conv: block = 64 pixels x 64 outputs, 256 threads.
// Phase 1 fuses the conv-partial combine + bias + 2*sigmoid.
// ---------------------------------------------------------------------------
__global__ void __launch_bounds__(256, 3) k_deform(
    float* __restrict__ out,
    const float* __restrict__ b_off, const float* __restrict__ b_mod)
{
    __shared__ __align__(16) float s_v[PBLK * VPITCH];
    __shared__ __align__(16) float s_w[4096];
    __shared__ float          s_cw[PBLK * 9][4];
    __shared__ unsigned short s_ci[PBLK * 9][4];

    int b   = blockIdx.y;
    int p0  = blockIdx.x * PBLK;
    int tid = threadIdx.x;

    const float* P0 = g_part + (size_t)(b * 2)     * 28 * HW;
    const float* P1 = g_part + (size_t)(b * 2 + 1) * 28 * HW;

    for (int i = tid; i < PBLK * 9; i += 256) {
        int pix = i / 9, tap = i % 9;
        int p = p0 + pix;
        int y = p / Ww, x = p % Ww;
        int ky = tap / 3, kx = tap % 3;
        float offy = P0[(2 * tap)     * HW + p] + P1[(2 * tap)     * HW + p]
                   + b_off[2 * tap];
        float offx = P0[(2 * tap + 1) * HW + p] + P1[(2 * tap + 1) * HW + p]
                   + b_off[2 * tap + 1];
        float zz   = P0[(18 + tap)    * HW + p] + P1[(18 + tap)    * HW + p]
                   + b_mod[tap];
        float m = 2.f / (1.f + expf(-zz));
        float py = (float)(y - 1 + ky) + offy;
        float px = (float)(x - 1 + kx) + offx;
        float fy = floorf(py), fx = floorf(px);
        int y0i = (int)fy, x0i = (int)fx;
        float wy = py - fy, wx = px - fx;
#pragma unroll
        for (int d = 0; d < 4; d++) {
            int dy = d >> 1, dx = d & 1;
            int yc = y0i + dy, xc = x0i + dx;
            bool ok = (yc >= 0) && (yc < Hh) && (xc >= 0) && (xc < Ww);
            float w = (dy ? wy : 1.f - wy) * (dx ? wx : 1.f - wx) * m;
            s_cw[i][d] = ok ? w : 0.f;
            int ycc = min(max(yc, 0), Hh - 1);
            int xcc = min(max(xc, 0), Ww - 1);
            s_ci[i][d] = (unsigned short)(ycc * Ww + xcc);
        }
    }

    unsigned long long a2[16];
#pragma unroll
    for (int oi = 0; oi < 16; oi++) a2[oi] = 0ull;

    int lane = tid & 31;
    int o0   = (tid >> 5) * 8;
    int gp   = tid >> 3;
    int gq   = tid & 7;
    const float* fb = g_fjt + (size_t)b * HW * Cc;

    __syncthreads();

    for (int tap = 0; tap < 9; tap++) {
        {
            const float4* src = (const float4*)(g_w2 + tap * 4096);
            float4* dst = (float4*)s_w;
#pragma unroll
            for (int i = 0; i < 4; i++)
                dst[tid + i * 256] = src[tid + i * 256];
        }
#pragma unroll
        for (int ph = 0; ph < 2; ph++) {
            int pix = gp + 32 * ph;
            int j = pix * 9 + tap;
            float w0 = s_cw[j][0], w1 = s_cw[j][1];
            float w2 = s_cw[j][2], w3 = s_cw[j][3];
            const float* pp0 = fb + (size_t)s_ci[j][0] * Cc;
            const float* pp1 = fb + (size_t)s_ci[j][1] * Cc;
            const float* pp2 = fb + (size_t)s_ci[j][2] * Cc;
            const float* pp3 = fb + (size_t)s_ci[j][3] * Cc;
#pragma unroll
            for (int qq = 0; qq < 2; qq++) {
                int q = gq + qq * 8;
                float4 f0 = *(const float4*)(pp0 + q * 4);
                float4 f1 = *(const float4*)(pp1 + q * 4);
                float4 f2 = *(const float4*)(pp2 + q * 4);
                float4 f3 = *(const float4*)(pp3 + q * 4);
                float4 v;
                v.x = w0 * f0.x + w1 * f1.x + w2 * f2.x + w3 * f3.x;
                v.y = w0 * f0.y + w1 * f1.y + w2 * f2.y + w3 * f3.y;
                v.z = w0 * f0.z + w1 * f1.z + w2 * f2.z + w3 * f3.z;
                v.w = w0 * f0.w + w1 * f1.w + w2 * f2.w + w3 * f3.w;
                *(float4*)(s_v + pix * VPITCH + q * 4) = v;
            }
        }
        __syncthreads();

        {
            const float* va = s_v + lane * VPITCH;
            const float* vb = s_v + (lane + 32) * VPITCH;
#pragma unroll 4
            for (int q = 0; q < 16; q++) {
                ulonglong2 ta = *(const ulonglong2*)(va + q * 4);
                ulonglong2 tb = *(const ulonglong2*)(vb + q * 4);
#pragma unroll
                for (int oi = 0; oi < 8; oi++) {
                    ulonglong2 wv = *(const ulonglong2*)(s_w + (q * 64 + o0 + oi) * 4);
                    unsigned long long x = a2[oi];
                    x = ffma2(ta.x, wv.x, x);
                    x = ffma2(ta.y, wv.y, x);
                    a2[oi] = x;
                    unsigned long long y2 = a2[8 + oi];
                    y2 = ffma2(tb.x, wv.x, y2);
                    y2 = ffma2(tb.y, wv.y, y2);
                    a2[8 + oi] = y2;
                }
            }
        }
        __syncthreads();
    }

#pragma unroll
    for (int oi = 0; oi < 8; oi++) {
        size_t base = (size_t)(b * 64 + o0 + oi) * HW + p0;
        float2 ua = unpack2(a2[oi]);
        float2 ub = unpack2(a2[8 + oi]);
        out[base + lane]      = ua.x + ua.y;
        out[base + 32 + lane] = ub.x + ub.y;
    }
}

// ---------------------------------------------------------------------------
extern "C" void kernel_launch(void* const* d_in, const int* in_sizes, int n_in,
                              void* d_out, int out_size) {
    const float* frame_i = (const float*)d_in[0];
    const float* frame_j = (const float*)d_in[1];
    const float* flow_ij = (const float*)d_in[2];
    const float* w_off   = (const float*)d_in[3];
    const float* b_off   = (const float*)d_in[4];
    const float* w_mod   = (const float*)d_in[5];
    const float* b_mod   = (const float*)d_in[6];
    const float* w_reg   = (const float*)d_in[7];
    float* out = (float*)d_out;

    k_transpose<<<dim3(HW / 32, Bn), 256>>>(frame_j);
    k_w2<<<(KK * 4096 + 255) / 256, 256>>>(w_reg);
    k_wc2<<<(66 * 560 + 255) / 256, 256>>>(w_off, w_mod);
    k_conv<<<dim3(Ww / 32, Hh / 8, Bn * 2), 256>>>(frame_i, frame_j, flow_ij);
    k_deform<<<dim3(HW / PBLK, Bn), 256>>>(out, b_off, b_mod);
}